// round 16
// baseline (speedup 1.0000x reference)
#include <cuda_runtime.h>
#include <math.h>

// ---------------- static configuration ----------------
#define BATCH   4
#define A_TOTAL 159882
#define NLEV    5
#define K_ALL   4507
#define POST_N  1000
#define IMG_WF  800.0f
#define IMG_HF  800.0f
#define MIN_SZ  0.001f
#define NMS_T   0.7f
#define BBOX_CLIP 4.135166556742356f
#define NW      16           // 64-bit words per suppression row (ceil(1000/64))
#define NINST   (BATCH * NLEV)
#define NBLK    148          // one block per SM; all resident -> spin-safe
#define FUNITS  (NINST * 16) // fill units: 64 rows each
#define SMEM_DYN 106496

__constant__ int c_n[NLEV]    = {120000, 30000, 7500, 1875, 507};
__constant__ int c_off[NLEV]  = {0, 120000, 150000, 157500, 159375};
__constant__ int c_k[NLEV]    = {1000, 1000, 1000, 1000, 507};
__constant__ int c_soff[NLEV] = {0, 1000, 2000, 3000, 4000};

// ---------------- scratch (device globals; zero-init at load) --------------
__device__ unsigned           g_hist  [NINST * 4096];
__device__ float4             g_boxv  [BATCH * K_ALL];
__device__ float              g_scorev[BATCH * K_ALL];
__device__ unsigned           g_keyv  [BATCH * K_ALL];
__device__ int                g_maxc  [BATCH];
__device__ unsigned long long g_sup   [NINST * 1000 * NW];
__device__ unsigned           g_rowmask[NINST * 1000];
__device__ unsigned long long g_keepbits[NINST * NW];
__device__ unsigned           g_barcnt[8];
__device__ unsigned           g_bargen[8];

__device__ __forceinline__ unsigned mono_bits(float f) {
    unsigned u = __float_as_uint(f);
    return (u & 0x80000000u) ? ~u : (u | 0x80000000u);
}

// software grid barrier (all NBLK blocks resident by construction)
__device__ __forceinline__ void grid_barrier(int id) {
    __syncthreads();
    if (threadIdx.x == 0) {
        __threadfence();
        unsigned gen = ((volatile unsigned*)g_bargen)[id];
        unsigned arr = atomicAdd(&g_barcnt[id], 1u);
        if (arr == NBLK - 1) {
            g_barcnt[id] = 0;
            __threadfence();
            atomicAdd(&g_bargen[id], 1u);
        } else {
            while (((volatile unsigned*)g_bargen)[id] == gen) __nanosleep(100);
        }
        __threadfence();
    }
    __syncthreads();
}

// suffix-scan threshold finder over a 4096-bin histogram (all threads call)
__device__ __forceinline__ int find_bucket(const unsigned* hist, int* sA, int* sB,
                                           int kneed, int t, int* shB) {
    sA[t] = (int)(hist[t * 4] + hist[t * 4 + 1] + hist[t * 4 + 2] + hist[t * 4 + 3]);
    __syncthreads();
    int* pin = sA; int* pout = sB;
    for (int d = 1; d < 1024; d <<= 1) {
        int v = pin[t];
        if (t + d < 1024) v += pin[t + d];
        pout[t] = v;
        __syncthreads();
        int* tmp = pin; pin = pout; pout = tmp;
    }
    int suffIncl  = pin[t];
    int suffAfter = (t < 1023) ? pin[t + 1] : 0;
    if (suffIncl >= kneed && suffAfter < kneed) {
        int cum = suffAfter, B = 4 * t;
        for (int bb = 4 * t + 3; bb >= 4 * t; bb--) {
            if (cum + (int)hist[bb] >= kneed) { B = bb; break; }
            cum += (int)hist[bb];
        }
        *shB = B;
    }
    __syncthreads();
    return *shB;
}

__device__ __forceinline__ void decode_one(unsigned long long key, int s,
                                           int img, int lvoff, int soff,
                                           const float* __restrict__ obj,
                                           const float4* __restrict__ deltas,
                                           const float4* __restrict__ anchors) {
    int j = (int)(~(unsigned)key);
    int idx = lvoff + j;
    int g = img * K_ALL + soff + s;

    float  o = obj[img * A_TOTAL + idx];
    float4 d = deltas[img * A_TOTAL + idx];
    float4 a = anchors[idx];

    float wa  = __fsub_rn(a.z, a.x);
    float ha  = __fsub_rn(a.w, a.y);
    float cxa = __fadd_rn(a.x, __fmul_rn(0.5f, wa));
    float cya = __fadd_rn(a.y, __fmul_rn(0.5f, ha));
    float dw  = fminf(d.z, BBOX_CLIP);
    float dh  = fminf(d.w, BBOX_CLIP);
    float cx  = __fadd_rn(__fmul_rn(d.x, wa), cxa);
    float cy  = __fadd_rn(__fmul_rn(d.y, ha), cya);
    float w   = __fmul_rn(expf(dw), wa);
    float h   = __fmul_rn(expf(dh), ha);
    float x1  = __fsub_rn(cx, __fmul_rn(0.5f, w));
    float y1  = __fsub_rn(cy, __fmul_rn(0.5f, h));
    float x2  = __fadd_rn(cx, __fmul_rn(0.5f, w));
    float y2  = __fadd_rn(cy, __fmul_rn(0.5f, h));

    float x1c = fminf(fmaxf(x1, 0.0f), IMG_WF);
    float y1c = fminf(fmaxf(y1, 0.0f), IMG_HF);
    float x2c = fminf(fmaxf(x2, 0.0f), IMG_WF);
    float y2c = fminf(fmaxf(y2, 0.0f), IMG_HF);

    float score = 1.0f / (1.0f + expf(-o));
    bool valid = (__fsub_rn(x2c, x1c) >= MIN_SZ) &&
                 (__fsub_rn(y2c, y1c) >= MIN_SZ) &&
                 (score >= 0.0f);

    g_boxv[g]   = make_float4(x1c, y1c, x2c, y2c);
    g_scorev[g] = score;
    g_keyv[g]   = valid ? mono_bits(o) : 0u;

    float mx = fmaxf(fmaxf(x1c, y1c), fmaxf(x2c, y2c));
    atomicMax(&g_maxc[img], __float_as_int(mx));
}

__device__ __forceinline__ bool pair_sup(float4 bi, float ai,
                                         const float4* sbox, const float* sar,
                                         int j, int i, int k) {
    if (j <= i || j >= k) return false;
    float4 bj = sbox[j];
    float lx = fmaxf(bi.x, bj.x), ly = fmaxf(bi.y, bj.y);
    float rx = fminf(bi.z, bj.z), ry = fminf(bi.w, bj.w);
    float ww = fmaxf(__fsub_rn(rx, lx), 0.0f);
    float hh = fmaxf(__fsub_rn(ry, ly), 0.0f);
    float inter = __fmul_rn(ww, hh);
    if (!(inter > 0.0f)) return false;
    float denom = __fsub_rn(__fadd_rn(ai, sar[j]), inter);
    float hib = __fmul_rn(denom, 0.7000070f);
    float lob = __fmul_rn(denom, 0.6999930f);
    if (inter > hib && denom >= 0.0f) return true;
    if (inter < lob) return false;
    return __fdiv_rn(inter, denom) > NMS_T;
}

__device__ __forceinline__ void fill_row(int i, int k, int inst,
                                         const float4* sbox, const float* sar,
                                         int lane) {
    if (i >= k) return;                    // warp-uniform (i per warp)
    float4 bi = sbox[i];
    float  ai = sar[i];
    unsigned long long* dst = &g_sup[(size_t)(inst * 1000 + i) * NW];
    unsigned mask = 0u;

    for (int w = i >> 6; w < NW; w++) {
        int j0 = w * 64 + lane;
        bool bA = pair_sup(bi, ai, sbox, sar, j0,      i, k);
        bool bB = pair_sup(bi, ai, sbox, sar, j0 + 32, i, k);
        unsigned m0 = __ballot_sync(0xffffffffu, bA);
        unsigned m1 = __ballot_sync(0xffffffffu, bB);
        unsigned long long wv = (unsigned long long)m0 | ((unsigned long long)m1 << 32);
        if (wv) {
            mask |= 1u << w;
            if (lane == 0) dst[w] = wv;
        }
    }
    if (lane == 0) g_rowmask[inst * 1000 + i] = mask;
}

extern __shared__ unsigned char dynsm[];

// ================= the one kernel =================
__global__ void __launch_bounds__(1024, 1)
rpn_kernel(const float* __restrict__ obj,
           const float4* __restrict__ deltas,
           const float4* __restrict__ anchors,
           float* __restrict__ out) {
    const int bid = blockIdx.x;
    const int t = threadIdx.x;
    const int lane = t & 31, wid = t >> 5;

    // ---------------- phase 1: histogram (all blocks) ----------------
    {
        const int nv = (BATCH * A_TOTAL) / 4;         // 159882 float4s
        for (int idx = bid * 1024 + t; idx < nv; idx += NBLK * 1024) {
            float4 f = ((const float4*)obj)[idx];
            float vals[4] = {f.x, f.y, f.z, f.w};
            int g0 = idx * 4;
            #pragma unroll
            for (int e = 0; e < 4; e++) {
                int g = g0 + e;
                int img = g / A_TOTAL;
                int r = g - img * A_TOTAL;
                int lev = (r < 120000) ? 0 : (r < 150000) ? 1 : (r < 157500) ? 2 :
                          (r < 159375) ? 3 : 4;
                unsigned u = mono_bits(vals[e]);
                atomicAdd(&g_hist[(img * NLEV + lev) * 4096 + (u >> 20)], 1u);
            }
        }
    }
    grid_barrier(0);

    // ---------------- phase 2: select (blocks 0..19) ----------------
    if (bid < NINST) {
        unsigned long long* cand = (unsigned long long*)dynsm;            // 64KB
        unsigned*           hist = (unsigned*)(dynsm + 65536);            // 16KB
        int*                sA   = (int*)(dynsm + 81920);
        int*                sB   = (int*)(dynsm + 86016);
        unsigned long long* sel  = (unsigned long long*)(dynsm + 90112);  // 16KB
        __shared__ int sh_B, sh_B2, sh_cnt, sh_above, sh_selcnt;

        const int inst = bid;
        const int img = inst / NLEV;
        const int lev = inst % NLEV;
        const int n = c_n[lev], lvoff = c_off[lev], k = c_k[lev], soff = c_soff[lev];
        const int start = img * A_TOTAL + lvoff;
        const float* __restrict__ src = obj + start;

        if (t == 0) { sh_cnt = 0; sh_above = 0; sh_selcnt = 0; }
        for (int b = t; b < 4096; b += 1024) {
            hist[b] = g_hist[inst * 4096 + b];
            g_hist[inst * 4096 + b] = 0u;       // re-zero for next replay
        }
        __syncthreads();

        const int B = find_bucket(hist, sA, sB, k, t, &sh_B);

        #define TESTC(val, jj) do {                                          \
            unsigned u_ = mono_bits(val);                                    \
            if ((int)(u_ >> 20) >= B) {                                      \
                int p_ = atomicAdd(&sh_cnt, 1);                              \
                if (p_ < 8192)                                               \
                    cand[p_] = ((unsigned long long)u_ << 32) |              \
                               (unsigned)(~(unsigned)(jj));                  \
            }                                                                \
        } while (0)
        {
            int a0 = (4 - (start & 3)) & 3;
            if (a0 > n) a0 = n;
            for (int j = t; j < a0; j += 1024) TESTC(src[j], j);
            const int nv = (n - a0) >> 2;
            const float4* src4 = (const float4*)(src + a0);
            for (int v = t; v < nv; v += 1024) {
                float4 f = src4[v];
                int j = a0 + v * 4;
                TESTC(f.x, j); TESTC(f.y, j + 1); TESTC(f.z, j + 2); TESTC(f.w, j + 3);
            }
            for (int j = a0 + (nv << 2) + t; j < n; j += 1024) TESTC(src[j], j);
        }
        #undef TESTC
        __syncthreads();

        const int cnt = (sh_cnt > 8192) ? 8192 : sh_cnt;

        for (int b = t; b < 4096; b += 1024) hist[b] = 0u;   // reuse as hist2
        __syncthreads();
        for (int i = t; i < cnt; i += 1024) {
            unsigned long long key = cand[i];
            int top = (int)(key >> 52);
            if (top > B) atomicAdd(&sh_above, 1);
            else         atomicAdd(&hist[(unsigned)(key >> 40) & 0xfffu], 1u);
        }
        __syncthreads();

        const int kneed2 = k - sh_above;
        const int B2 = find_bucket(hist, sA, sB, kneed2, t, &sh_B2);

        for (int i = t; i < cnt; i += 1024) {
            unsigned long long key = cand[i];
            int top = (int)(key >> 52);
            int mid = (int)((key >> 40) & 0xfffu);
            if (top > B || mid >= B2) {
                int p = atomicAdd(&sh_selcnt, 1);
                if (p < 2048) sel[p] = key;
            }
        }
        __syncthreads();

        const int m = (sh_selcnt > 2048) ? 2048 : sh_selcnt;

        unsigned long long k0 = (t < m) ? sel[t] : 0ULL;
        unsigned long long k1 = (t + 1024 < m) ? sel[t + 1024] : 0ULL;
        int r0 = 0, r1 = 0;
        if (m <= 1024) {
            for (int i = 0; i < m; i++) r0 += (sel[i] > k0);
        } else {
            for (int i = 0; i < m; i++) {
                unsigned long long v = sel[i];
                r0 += (v > k0); r1 += (v > k1);
            }
        }

        if (t < m && r0 < k)        decode_one(k0, r0, img, lvoff, soff, obj, deltas, anchors);
        if (t + 1024 < m && r1 < k) decode_one(k1, r1, img, lvoff, soff, obj, deltas, anchors);
    }
    grid_barrier(1);

    // ---------------- phase 3: fill (all blocks, contiguous unit ranges) ----
    {
        float4* sbox = (float4*)dynsm;                 // 16KB
        float*  sar  = (float*)(dynsm + 16000);        // 4KB

        int lo = (bid * FUNITS) / NBLK;
        int hi = ((bid + 1) * FUNITS) / NBLK;
        int curinst = -1;
        for (int u = lo; u < hi; u++) {
            const int inst = u >> 4;
            const int rb   = u & 15;
            const int img  = inst / NLEV, lev = inst % NLEV;
            const int k = c_k[lev], soff = c_soff[lev];
            const int base = img * K_ALL + soff;
            if (rb * 64 >= k) continue;

            if (inst != curinst) {
                __syncthreads();           // previous unit done reading sbox
                float maxc = __int_as_float(g_maxc[img]);
                float off  = __fmul_rn((float)lev, __fadd_rn(maxc, 1.0f));
                for (int j = t; j < k; j += 1024) {
                    float4 b = g_boxv[base + j];
                    float x1 = __fadd_rn(b.x, off), y1 = __fadd_rn(b.y, off);
                    float x2 = __fadd_rn(b.z, off), y2 = __fadd_rn(b.w, off);
                    sbox[j] = make_float4(x1, y1, x2, y2);
                    sar[j]  = __fmul_rn(__fsub_rn(x2, x1), __fsub_rn(y2, y1));
                }
                __syncthreads();
                curinst = inst;
            }
            fill_row(rb * 64 + wid,      k, inst, sbox, sar, lane);
            fill_row(rb * 64 + wid + 32, k, inst, sbox, sar, lane);
        }
    }
    grid_barrier(2);

    // ---------------- phase 4: scan (blocks 0..19) ----------------
    if (bid < NINST) {
        unsigned*           srm    = (unsigned*)dynsm;            // 4KB
        unsigned long long* sdiagw = (unsigned long long*)(dynsm + 4096);  // 8KB
        __shared__ unsigned long long skeep[NW], sdmask[NW];
        __shared__ unsigned sv[32], sd[32];
        __shared__ unsigned long long s_alive;

        const int inst = bid;
        const int img = inst / NLEV, lev = inst % NLEV;
        const int k = c_k[lev], soff = c_soff[lev];
        const int base = img * K_ALL + soff;

        {
            int r = t;
            bool valid = false, dact = false;
            unsigned m = 0;
            if (r < k) {
                valid = (g_keyv[base + r] != 0u);
                m = g_rowmask[inst * 1000 + r];
                dact = (m >> (r >> 6)) & 1u;
            }
            srm[r] = m;
            sdiagw[r] = dact ? g_sup[(size_t)(inst * 1000 + r) * NW + (r >> 6)] : 0ULL;
            unsigned bv = __ballot_sync(0xffffffffu, valid);
            unsigned bd = __ballot_sync(0xffffffffu, dact);
            if (lane == 0) { sv[wid] = bv; sd[wid] = bd; }
        }
        __syncthreads();
        if (t < NW) {
            skeep[t]  = (unsigned long long)sv[2 * t] | ((unsigned long long)sv[2 * t + 1] << 32);
            sdmask[t] = (unsigned long long)sd[2 * t] | ((unsigned long long)sd[2 * t + 1] << 32);
        }
        __syncthreads();

        const int NCH = (k + 63) >> 6;

        unsigned long long p0 = 0, p1 = 0;
        if (wid > 0 && wid < NW) {
            int r0 = lane, r1 = lane + 32;
            if (r0 < k && ((srm[r0] >> wid) & 1u))
                p0 = g_sup[(size_t)(inst * 1000 + r0) * NW + wid];
            if (r1 < k && ((srm[r1] >> wid) & 1u))
                p1 = g_sup[(size_t)(inst * 1000 + r1) * NW + wid];
        }

        for (int c = 0; c < NCH; c++) {
            if (t == 0) {
                unsigned long long alive = skeep[c];
                unsigned long long dm = sdmask[c];
                while (dm) {
                    int bidx[8]; unsigned long long rw[8]; int cnt = 0;
                    #pragma unroll
                    for (int e = 0; e < 8; e++) {
                        if (!dm) break;
                        int b = __ffsll((long long)dm) - 1;
                        dm &= dm - 1ULL;
                        bidx[cnt] = b;
                        rw[cnt] = sdiagw[c * 64 + b];
                        cnt++;
                    }
                    for (int e = 0; e < cnt; e++)
                        if ((alive >> bidx[e]) & 1ULL) alive &= ~rw[e];
                }
                skeep[c] = alive;
                s_alive = alive;
            }
            __syncthreads();
            const unsigned long long alive = s_alive;

            if (wid < NW) {
                unsigned long long v = 0;
                if (wid > c) {
                    if ((alive >> lane) & 1ULL)        v  = p0;
                    if ((alive >> (lane + 32)) & 1ULL) v |= p1;
                }

                p0 = p1 = 0;
                int cn = c + 1;
                if (cn < NCH && wid > cn) {
                    int r0 = cn * 64 + lane, r1 = r0 + 32;
                    if (r0 < k && ((srm[r0] >> wid) & 1u))
                        p0 = g_sup[(size_t)(inst * 1000 + r0) * NW + wid];
                    if (r1 < k && ((srm[r1] >> wid) & 1u))
                        p1 = g_sup[(size_t)(inst * 1000 + r1) * NW + wid];
                }

                unsigned lo2 = __reduce_or_sync(0xffffffffu, (unsigned)v);
                unsigned hi2 = __reduce_or_sync(0xffffffffu, (unsigned)(v >> 32));
                if (lane == 0) {
                    unsigned long long vv = ((unsigned long long)hi2 << 32) | lo2;
                    if (vv) skeep[wid] &= ~vv;
                }
            }
            __syncthreads();
        }

        if (t < NW) g_keepbits[inst * NW + t] = skeep[t];
    }
    grid_barrier(3);

    // ---------------- phase 5: final (blocks 0..19) ----------------
    if (bid < NINST) {
        unsigned long long* klist = (unsigned long long*)dynsm;   // 36KB
        __shared__ int lvbase[NLEV + 1];
        __shared__ int warpsum[32];

        const int inst = bid;
        const int img = inst / NLEV, mylev = inst % NLEV;

        if (t == 0) lvbase[0] = 0;
        __syncthreads();

        for (int lev = 0; lev < NLEV; lev++) {
            const int k = c_k[lev], soff = c_soff[lev];
            bool kept = false;
            unsigned long long key = 0ULL;
            if (t < k) {
                unsigned long long kb = g_keepbits[(img * NLEV + lev) * NW + (t >> 6)];
                if ((kb >> (t & 63)) & 1ULL) {
                    int slot = soff + t;
                    kept = true;
                    key = ((unsigned long long)g_keyv[img * K_ALL + slot] << 32) |
                          (unsigned)(~(unsigned)slot);
                }
            }
            unsigned bm = __ballot_sync(0xffffffffu, kept);
            if (lane == 0) warpsum[wid] = __popc(bm);
            __syncthreads();
            if (t < 32) {
                int v = warpsum[t];
                for (int d = 1; d < 32; d <<= 1) {
                    int o = __shfl_up_sync(0xffffffffu, v, d);
                    if (t >= d) v += o;
                }
                warpsum[t] = v;
                if (t == 31) lvbase[lev + 1] = lvbase[lev] + v;
            }
            __syncthreads();
            if (kept) {
                int pos = lvbase[lev] + (wid ? warpsum[wid - 1] : 0) +
                          __popc(bm & ((1u << lane) - 1u));
                klist[pos] = key;
            }
            __syncthreads();
        }

        const int C = lvbase[NLEV];

        for (int c = lvbase[mylev] + t; c < lvbase[mylev + 1]; c += 1024) {
            unsigned long long key = klist[c];
            int rank = c - lvbase[mylev];
            #pragma unroll
            for (int l2 = 0; l2 < NLEV; l2++) {
                if (l2 == mylev) continue;
                int lo = lvbase[l2], hi = lvbase[l2 + 1];
                while (lo < hi) {
                    int mid = (lo + hi) >> 1;
                    if (klist[mid] > key) lo = mid + 1; else hi = mid;
                }
                rank += lo - lvbase[l2];
            }
            if (rank < POST_N) {
                int slot = (int)(~(unsigned)key);
                float4 b = g_boxv[img * K_ALL + slot];
                float sc = g_scorev[img * K_ALL + slot];
                float* ob = out + (size_t)(img * POST_N + rank) * 4;
                ob[0] = b.x; ob[1] = b.y; ob[2] = b.z; ob[3] = b.w;
                out[BATCH * POST_N * 4 + img * POST_N + rank] = sc;
            }
        }

        if (mylev == 0) {
            for (int x = C + t; x < POST_N; x += 1024) {
                float* ob = out + (size_t)(img * POST_N + x) * 4;
                ob[0] = 0.f; ob[1] = 0.f; ob[2] = 0.f; ob[3] = 0.f;
                out[BATCH * POST_N * 4 + img * POST_N + x] = 0.f;
            }
            if (t == 0) g_maxc[img] = 0;
        }
    }
}

// ================= launch ====================
extern "C" void kernel_launch(void* const* d_in, const int* in_sizes, int n_in,
                              void* d_out, int out_size) {
    const float*  obj     = (const float*) d_in[0];   // [4, 159882]
    const float4* deltas  = (const float4*)d_in[1];   // [4, 159882, 4]
    const float4* anchors = (const float4*)d_in[2];   // [159882, 4]
    float* out = (float*)d_out;                       // boxes[4,1000,4] ++ scores[4,1000]

    cudaFuncSetAttribute(rpn_kernel, cudaFuncAttributeMaxDynamicSharedMemorySize, SMEM_DYN);
    rpn_kernel<<<NBLK, 1024, SMEM_DYN>>>(obj, deltas, anchors, out);
}

// round 17
// speedup vs baseline: 1.0480x; 1.0480x over previous
#include <cuda_runtime.h>
#include <math.h>

// ---------------- static configuration ----------------
#define BATCH   4
#define A_TOTAL 159882
#define NLEV    5
#define K_ALL   4507
#define POST_N  1000
#define IMG_WF  800.0f
#define IMG_HF  800.0f
#define MIN_SZ  0.001f
#define NMS_T   0.7f
#define BBOX_CLIP 4.135166556742356f
#define FILL_RB 16           // row-blocks of 64 rows (2 per warp) per (img,lev)
#define NW      16           // 64-bit words per suppression row (ceil(1000/64))
#define NINST   (BATCH * NLEV)
#define NBLK    148          // node-1 grid: one block per SM, all resident

__constant__ int c_n[NLEV]    = {120000, 30000, 7500, 1875, 507};
__constant__ int c_off[NLEV]  = {0, 120000, 150000, 157500, 159375};
__constant__ int c_k[NLEV]    = {1000, 1000, 1000, 1000, 507};
__constant__ int c_soff[NLEV] = {0, 1000, 2000, 3000, 4000};

// ---------------- scratch (device globals; zero-init at load) --------------
__device__ unsigned           g_hist  [NINST * 4096];
__device__ float4             g_boxv  [BATCH * K_ALL];
__device__ float              g_scorev[BATCH * K_ALL];
__device__ unsigned           g_keyv  [BATCH * K_ALL];
__device__ int                g_maxc  [BATCH];
__device__ unsigned long long g_sup   [NINST * 1000 * NW];
__device__ unsigned           g_rowmask[NINST * 1000];
__device__ unsigned long long g_keepbits[NINST * NW];
__device__ int                g_fillcnt[NINST];
__device__ int                g_imgcnt[BATCH];
__device__ unsigned           g_hcnt;

__device__ __forceinline__ unsigned mono_bits(float f) {
    unsigned u = __float_as_uint(f);
    return (u & 0x80000000u) ? ~u : (u | 0x80000000u);
}

extern __shared__ unsigned char dynsm[];

// suffix-scan threshold finder over a 4096-bin histogram (all threads call)
__device__ __forceinline__ int find_bucket(const unsigned* hist, int* sA, int* sB,
                                           int kneed, int t, int* shB) {
    sA[t] = (int)(hist[t * 4] + hist[t * 4 + 1] + hist[t * 4 + 2] + hist[t * 4 + 3]);
    __syncthreads();
    int* pin = sA; int* pout = sB;
    for (int d = 1; d < 1024; d <<= 1) {
        int v = pin[t];
        if (t + d < 1024) v += pin[t + d];
        pout[t] = v;
        __syncthreads();
        int* tmp = pin; pin = pout; pout = tmp;
    }
    int suffIncl  = pin[t];
    int suffAfter = (t < 1023) ? pin[t + 1] : 0;
    if (suffIncl >= kneed && suffAfter < kneed) {
        int cum = suffAfter, B = 4 * t;
        for (int bb = 4 * t + 3; bb >= 4 * t; bb--) {
            if (cum + (int)hist[bb] >= kneed) { B = bb; break; }
            cum += (int)hist[bb];
        }
        *shB = B;
    }
    __syncthreads();
    return *shB;
}

__device__ __forceinline__ void decode_one(unsigned long long key, int s,
                                           int img, int lvoff, int soff,
                                           const float* __restrict__ obj,
                                           const float4* __restrict__ deltas,
                                           const float4* __restrict__ anchors) {
    int j = (int)(~(unsigned)key);
    int idx = lvoff + j;
    int g = img * K_ALL + soff + s;

    float  o = obj[img * A_TOTAL + idx];
    float4 d = deltas[img * A_TOTAL + idx];
    float4 a = anchors[idx];

    float wa  = __fsub_rn(a.z, a.x);
    float ha  = __fsub_rn(a.w, a.y);
    float cxa = __fadd_rn(a.x, __fmul_rn(0.5f, wa));
    float cya = __fadd_rn(a.y, __fmul_rn(0.5f, ha));
    float dw  = fminf(d.z, BBOX_CLIP);
    float dh  = fminf(d.w, BBOX_CLIP);
    float cx  = __fadd_rn(__fmul_rn(d.x, wa), cxa);
    float cy  = __fadd_rn(__fmul_rn(d.y, ha), cya);
    float w   = __fmul_rn(expf(dw), wa);
    float h   = __fmul_rn(expf(dh), ha);
    float x1  = __fsub_rn(cx, __fmul_rn(0.5f, w));
    float y1  = __fsub_rn(cy, __fmul_rn(0.5f, h));
    float x2  = __fadd_rn(cx, __fmul_rn(0.5f, w));
    float y2  = __fadd_rn(cy, __fmul_rn(0.5f, h));

    float x1c = fminf(fmaxf(x1, 0.0f), IMG_WF);
    float y1c = fminf(fmaxf(y1, 0.0f), IMG_HF);
    float x2c = fminf(fmaxf(x2, 0.0f), IMG_WF);
    float y2c = fminf(fmaxf(y2, 0.0f), IMG_HF);

    float score = 1.0f / (1.0f + expf(-o));
    bool valid = (__fsub_rn(x2c, x1c) >= MIN_SZ) &&
                 (__fsub_rn(y2c, y1c) >= MIN_SZ) &&
                 (score >= 0.0f);

    g_boxv[g]   = make_float4(x1c, y1c, x2c, y2c);
    g_scorev[g] = score;
    g_keyv[g]   = valid ? mono_bits(o) : 0u;

    float mx = fmaxf(fmaxf(x1c, y1c), fmaxf(x2c, y2c));
    atomicMax(&g_maxc[img], __float_as_int(mx));
}

// ================= Node 1: histogram (all blocks) + select (blocks 0..19) ==
__global__ void __launch_bounds__(1024, 1)
selhist_kernel(const float* __restrict__ obj,
               const float4* __restrict__ deltas,
               const float4* __restrict__ anchors) {
    const int bid = blockIdx.x;
    const int t = threadIdx.x;

    // ---- phase A: grid-stride histogram ----
    {
        const int nv = (BATCH * A_TOTAL) / 4;          // 159882 float4s
        for (int idx = bid * 1024 + t; idx < nv; idx += NBLK * 1024) {
            float4 f = ((const float4*)obj)[idx];
            float vals[4] = {f.x, f.y, f.z, f.w};
            int g0 = idx * 4;
            #pragma unroll
            for (int e = 0; e < 4; e++) {
                int g = g0 + e;
                int img = g / A_TOTAL;
                int r = g - img * A_TOTAL;
                int lev = (r < 120000) ? 0 : (r < 150000) ? 1 : (r < 157500) ? 2 :
                          (r < 159375) ? 3 : 4;
                unsigned u = mono_bits(vals[e]);
                atomicAdd(&g_hist[(img * NLEV + lev) * 4096 + (u >> 20)], 1u);
            }
        }
    }
    __threadfence();
    __syncthreads();
    if (t == 0) atomicAdd(&g_hcnt, 1u);
    if (bid >= NINST) return;

    // waiters (all 148 blocks resident by construction -> no deadlock)
    if (t == 0) {
        while (((volatile unsigned*)&g_hcnt)[0] < NBLK) __nanosleep(64);
        __threadfence();
    }
    __syncthreads();

    // ---- phase B: select (instance = bid) ----
    unsigned long long* cand = (unsigned long long*)dynsm;            // 64KB
    unsigned*           hist = (unsigned*)(dynsm + 65536);            // 16KB
    int*                sA   = (int*)(dynsm + 81920);
    int*                sB   = (int*)(dynsm + 86016);
    unsigned long long* sel  = (unsigned long long*)(dynsm + 90112);  // 16KB
    __shared__ int sh_B, sh_B2, sh_cnt, sh_above, sh_selcnt;

    const int inst = bid;
    const int img = inst / NLEV;
    const int lev = inst % NLEV;
    const int n = c_n[lev], lvoff = c_off[lev], k = c_k[lev], soff = c_soff[lev];
    const int start = img * A_TOTAL + lvoff;
    const float* __restrict__ src = obj + start;

    if (t == 0) { sh_cnt = 0; sh_above = 0; sh_selcnt = 0; }
    for (int b = t; b < 4096; b += 1024) {
        hist[b] = g_hist[inst * 4096 + b];
        g_hist[inst * 4096 + b] = 0u;       // re-zero for next replay
    }
    __syncthreads();

    const int B = find_bucket(hist, sA, sB, k, t, &sh_B);

    #define TESTC(val, jj) do {                                          \
        unsigned u_ = mono_bits(val);                                    \
        if ((int)(u_ >> 20) >= B) {                                      \
            int p_ = atomicAdd(&sh_cnt, 1);                              \
            if (p_ < 8192)                                               \
                cand[p_] = ((unsigned long long)u_ << 32) |              \
                           (unsigned)(~(unsigned)(jj));                  \
        }                                                                \
    } while (0)
    {
        int a0 = (4 - (start & 3)) & 3;
        if (a0 > n) a0 = n;
        for (int j = t; j < a0; j += 1024) TESTC(src[j], j);
        const int nv = (n - a0) >> 2;
        const float4* src4 = (const float4*)(src + a0);
        for (int v = t; v < nv; v += 1024) {
            float4 f = src4[v];
            int j = a0 + v * 4;
            TESTC(f.x, j); TESTC(f.y, j + 1); TESTC(f.z, j + 2); TESTC(f.w, j + 3);
        }
        for (int j = a0 + (nv << 2) + t; j < n; j += 1024) TESTC(src[j], j);
    }
    #undef TESTC
    __syncthreads();

    const int cnt = (sh_cnt > 8192) ? 8192 : sh_cnt;

    for (int b = t; b < 4096; b += 1024) hist[b] = 0u;   // reuse as hist2
    __syncthreads();
    for (int i = t; i < cnt; i += 1024) {
        unsigned long long key = cand[i];
        int top = (int)(key >> 52);
        if (top > B) atomicAdd(&sh_above, 1);
        else         atomicAdd(&hist[(unsigned)(key >> 40) & 0xfffu], 1u);
    }
    __syncthreads();

    const int kneed2 = k - sh_above;
    const int B2 = find_bucket(hist, sA, sB, kneed2, t, &sh_B2);

    for (int i = t; i < cnt; i += 1024) {
        unsigned long long key = cand[i];
        int top = (int)(key >> 52);
        int mid = (int)((key >> 40) & 0xfffu);
        if (top > B || mid >= B2) {
            int p = atomicAdd(&sh_selcnt, 1);
            if (p < 2048) sel[p] = key;
        }
    }
    __syncthreads();

    const int m = (sh_selcnt > 2048) ? 2048 : sh_selcnt;

    // counting rank (rank = #greater); keys unique -> exact permutation
    unsigned long long k0 = (t < m) ? sel[t] : 0ULL;
    unsigned long long k1 = (t + 1024 < m) ? sel[t + 1024] : 0ULL;
    int r0 = 0, r1 = 0;
    if (m <= 1024) {
        for (int i = 0; i < m; i++) r0 += (sel[i] > k0);
    } else {
        for (int i = 0; i < m; i++) {
            unsigned long long v = sel[i];
            r0 += (v > k0); r1 += (v > k1);
        }
    }

    if (t < m && r0 < k)        decode_one(k0, r0, img, lvoff, soff, obj, deltas, anchors);
    if (t + 1024 < m && r1 < k) decode_one(k1, r1, img, lvoff, soff, obj, deltas, anchors);
}

// ================= Node 2: fill + scan (last block) + final (last image) ===
__device__ __forceinline__ bool pair_sup(float4 bi, float ai,
                                         const float4* sbox, const float* sar,
                                         int j, int i, int k) {
    if (j <= i || j >= k) return false;
    float4 bj = sbox[j];
    float lx = fmaxf(bi.x, bj.x), ly = fmaxf(bi.y, bj.y);
    float rx = fminf(bi.z, bj.z), ry = fminf(bi.w, bj.w);
    float ww = fmaxf(__fsub_rn(rx, lx), 0.0f);
    float hh = fmaxf(__fsub_rn(ry, ly), 0.0f);
    float inter = __fmul_rn(ww, hh);
    if (!(inter > 0.0f)) return false;
    float denom = __fsub_rn(__fadd_rn(ai, sar[j]), inter);
    float hib = __fmul_rn(denom, 0.7000070f);
    float lob = __fmul_rn(denom, 0.6999930f);
    if (inter > hib && denom >= 0.0f) return true;
    if (inter < lob) return false;
    return __fdiv_rn(inter, denom) > NMS_T;
}

__device__ __forceinline__ void fill_row(int i, int k, int inst,
                                         const float4* sbox, const float* sar,
                                         int lane) {
    if (i >= k) return;                    // warp-uniform (i per warp)
    float4 bi = sbox[i];
    float  ai = sar[i];
    unsigned long long* dst = &g_sup[(size_t)(inst * 1000 + i) * NW];
    unsigned mask = 0u;

    for (int w = i >> 6; w < NW; w++) {
        int j0 = w * 64 + lane;
        bool bA = pair_sup(bi, ai, sbox, sar, j0,      i, k);
        bool bB = pair_sup(bi, ai, sbox, sar, j0 + 32, i, k);
        unsigned m0 = __ballot_sync(0xffffffffu, bA);
        unsigned m1 = __ballot_sync(0xffffffffu, bB);
        unsigned long long wv = (unsigned long long)m0 | ((unsigned long long)m1 << 32);
        if (wv) {
            mask |= 1u << w;
            if (lane == 0) dst[w] = wv;
        }
    }
    if (lane == 0) g_rowmask[inst * 1000 + i] = mask;
}

__global__ void __launch_bounds__(1024)
fsf_kernel(float* __restrict__ out) {
    // dynamic smem (40960B), aliased per phase:
    //   fill : sbox[1000] f4 @0 (16KB), sar[1000] f @16000 (4KB)
    //   scan : srm[1024] u32 @20480, sdiagw[1024] u64 @24576
    //   final: klist[K_ALL] u64 @0 (36KB)
    float4*             sbox   = (float4*)dynsm;
    float*              sar    = (float*)(dynsm + 16000);
    unsigned*           srm    = (unsigned*)(dynsm + 20480);
    unsigned long long* sdiagw = (unsigned long long*)(dynsm + 24576);
    unsigned long long* klist  = (unsigned long long*)dynsm;

    __shared__ unsigned long long skeep[NW], sdmask[NW];
    __shared__ unsigned sv[32], sd[32];
    __shared__ unsigned long long s_alive;
    __shared__ int s_last, s_dofinal;
    __shared__ int lvbase[NLEV + 1];
    __shared__ int warpsum[32];

    const int bid  = blockIdx.x;
    const int inst = bid / FILL_RB;
    const int rb   = bid % FILL_RB;
    const int img  = inst / NLEV, lev = inst % NLEV;
    const int k = c_k[lev], soff = c_soff[lev];
    const int base = img * K_ALL + soff;
    const int t = threadIdx.x;
    const int lane = t & 31, wid = t >> 5;

    if (bid == 0 && t == 0) g_hcnt = 0;        // reset node-1 counter for next replay

    // ---- fill ----
    const bool haswork = (rb * 64 < k);
    if (haswork) {
        float maxc = __int_as_float(g_maxc[img]);
        float off  = __fmul_rn((float)lev, __fadd_rn(maxc, 1.0f));
        for (int j = t; j < k; j += 1024) {
            float4 b = g_boxv[base + j];
            float x1 = __fadd_rn(b.x, off), y1 = __fadd_rn(b.y, off);
            float x2 = __fadd_rn(b.z, off), y2 = __fadd_rn(b.w, off);
            sbox[j] = make_float4(x1, y1, x2, y2);
            sar[j]  = __fmul_rn(__fsub_rn(x2, x1), __fsub_rn(y2, y1));
        }
        __syncthreads();
        fill_row(rb * 64 + wid,      k, inst, sbox, sar, lane);
        fill_row(rb * 64 + wid + 32, k, inst, sbox, sar, lane);
    }

    // ---- last-block handoff -> scan ----
    __threadfence();
    __syncthreads();
    if (t == 0) s_last = (atomicAdd(&g_fillcnt[inst], 1) == FILL_RB - 1) ? 1 : 0;
    __syncthreads();
    if (!s_last) return;
    if (t == 0) g_fillcnt[inst] = 0;

    {
        int r = t;
        bool valid = false, dact = false;
        unsigned m = 0;
        if (r < k) {
            valid = (g_keyv[base + r] != 0u);
            m = g_rowmask[inst * 1000 + r];
            dact = (m >> (r >> 6)) & 1u;
        }
        srm[r] = m;
        sdiagw[r] = dact ? g_sup[(size_t)(inst * 1000 + r) * NW + (r >> 6)] : 0ULL;
        unsigned bv = __ballot_sync(0xffffffffu, valid);
        unsigned bd = __ballot_sync(0xffffffffu, dact);
        if (lane == 0) { sv[wid] = bv; sd[wid] = bd; }
    }
    __syncthreads();
    if (t < NW) {
        skeep[t]  = (unsigned long long)sv[2 * t] | ((unsigned long long)sv[2 * t + 1] << 32);
        sdmask[t] = (unsigned long long)sd[2 * t] | ((unsigned long long)sd[2 * t + 1] << 32);
    }
    __syncthreads();

    const int NCH = (k + 63) >> 6;

    unsigned long long p0 = 0, p1 = 0;
    if (wid > 0 && wid < NW) {
        int r0 = lane, r1 = lane + 32;
        if (r0 < k && ((srm[r0] >> wid) & 1u))
            p0 = g_sup[(size_t)(inst * 1000 + r0) * NW + wid];
        if (r1 < k && ((srm[r1] >> wid) & 1u))
            p1 = g_sup[(size_t)(inst * 1000 + r1) * NW + wid];
    }

    for (int c = 0; c < NCH; c++) {
        if (t == 0) {
            unsigned long long alive = skeep[c];
            unsigned long long dm = sdmask[c];
            while (dm) {
                int bidx[8]; unsigned long long rw[8]; int cnt = 0;
                #pragma unroll
                for (int e = 0; e < 8; e++) {
                    if (!dm) break;
                    int b = __ffsll((long long)dm) - 1;
                    dm &= dm - 1ULL;
                    bidx[cnt] = b;
                    rw[cnt] = sdiagw[c * 64 + b];
                    cnt++;
                }
                for (int e = 0; e < cnt; e++)
                    if ((alive >> bidx[e]) & 1ULL) alive &= ~rw[e];
            }
            skeep[c] = alive;
            s_alive = alive;
        }
        __syncthreads();
        const unsigned long long alive = s_alive;

        if (wid < NW) {
            unsigned long long v = 0;
            if (wid > c) {
                if ((alive >> lane) & 1ULL)        v  = p0;
                if ((alive >> (lane + 32)) & 1ULL) v |= p1;
            }

            p0 = p1 = 0;
            int cn = c + 1;
            if (cn < NCH && wid > cn) {
                int r0 = cn * 64 + lane, r1 = r0 + 32;
                if (r0 < k && ((srm[r0] >> wid) & 1u))
                    p0 = g_sup[(size_t)(inst * 1000 + r0) * NW + wid];
                if (r1 < k && ((srm[r1] >> wid) & 1u))
                    p1 = g_sup[(size_t)(inst * 1000 + r1) * NW + wid];
            }

            unsigned lo2 = __reduce_or_sync(0xffffffffu, (unsigned)v);
            unsigned hi2 = __reduce_or_sync(0xffffffffu, (unsigned)(v >> 32));
            if (lane == 0) {
                unsigned long long vv = ((unsigned long long)hi2 << 32) | lo2;
                if (vv) skeep[wid] &= ~vv;
            }
        }
        __syncthreads();
    }

    if (t < NW) g_keepbits[inst * NW + t] = skeep[t];

    // ---- last-image handoff -> final ----
    __threadfence();
    __syncthreads();
    if (t == 0) {
        int arr = atomicAdd(&g_imgcnt[img], 1);
        s_dofinal = (arr == NLEV - 1) ? 1 : 0;
        if (s_dofinal) g_imgcnt[img] = 0;
    }
    __syncthreads();
    if (!s_dofinal) return;
    __threadfence();       // acquire: see other instances' keepbits
    __syncthreads();

    // ---- final (whole image, this block) ----
    if (t == 0) lvbase[0] = 0;
    __syncthreads();

    for (int l = 0; l < NLEV; l++) {
        const int kk = c_k[l], so = c_soff[l];
        bool kept = false;
        unsigned long long key = 0ULL;
        if (t < kk) {
            unsigned long long kb = g_keepbits[(img * NLEV + l) * NW + (t >> 6)];
            if ((kb >> (t & 63)) & 1ULL) {
                int slot = so + t;
                kept = true;
                key = ((unsigned long long)g_keyv[img * K_ALL + slot] << 32) |
                      (unsigned)(~(unsigned)slot);
            }
        }
        unsigned bm = __ballot_sync(0xffffffffu, kept);
        if (lane == 0) warpsum[wid] = __popc(bm);
        __syncthreads();
        if (t < 32) {
            int v = warpsum[t];
            for (int d = 1; d < 32; d <<= 1) {
                int o = __shfl_up_sync(0xffffffffu, v, d);
                if (t >= d) v += o;
            }
            warpsum[t] = v;
            if (t == 31) lvbase[l + 1] = lvbase[l] + v;
        }
        __syncthreads();
        if (kept) {
            int pos = lvbase[l] + (wid ? warpsum[wid - 1] : 0) +
                      __popc(bm & ((1u << lane) - 1u));
            klist[pos] = key;
        }
        __syncthreads();
    }

    const int C = lvbase[NLEV];

    for (int c = t; c < C; c += 1024) {
        int l = 0;
        while (l < NLEV - 1 && c >= lvbase[l + 1]) l++;
        unsigned long long key = klist[c];
        int rank = c - lvbase[l];
        #pragma unroll
        for (int l2 = 0; l2 < NLEV; l2++) {
            if (l2 == l) continue;
            int lo = lvbase[l2], hi = lvbase[l2 + 1];
            while (lo < hi) {
                int mid = (lo + hi) >> 1;
                if (klist[mid] > key) lo = mid + 1; else hi = mid;
            }
            rank += lo - lvbase[l2];
        }
        if (rank < POST_N) {
            int slot = (int)(~(unsigned)key);
            float4 b = g_boxv[img * K_ALL + slot];
            float sc = g_scorev[img * K_ALL + slot];
            float* ob = out + (size_t)(img * POST_N + rank) * 4;
            ob[0] = b.x; ob[1] = b.y; ob[2] = b.z; ob[3] = b.w;
            out[BATCH * POST_N * 4 + img * POST_N + rank] = sc;
        }
    }

    for (int x = C + t; x < POST_N; x += 1024) {
        float* ob = out + (size_t)(img * POST_N + x) * 4;
        ob[0] = 0.f; ob[1] = 0.f; ob[2] = 0.f; ob[3] = 0.f;
        out[BATCH * POST_N * 4 + img * POST_N + x] = 0.f;
    }
    if (t == 0) g_maxc[img] = 0;    // reset for next replay
}

// ================= launch ====================
extern "C" void kernel_launch(void* const* d_in, const int* in_sizes, int n_in,
                              void* d_out, int out_size) {
    const float*  obj     = (const float*) d_in[0];   // [4, 159882]
    const float4* deltas  = (const float4*)d_in[1];   // [4, 159882, 4]
    const float4* anchors = (const float4*)d_in[2];   // [159882, 4]
    float* out = (float*)d_out;                       // boxes[4,1000,4] ++ scores[4,1000]

    cudaFuncSetAttribute(selhist_kernel, cudaFuncAttributeMaxDynamicSharedMemorySize, 106496);
    cudaFuncSetAttribute(fsf_kernel,     cudaFuncAttributeMaxDynamicSharedMemorySize, 40960);

    selhist_kernel<<<NBLK, 1024, 106496>>>(obj, deltas, anchors);
    fsf_kernel<<<NINST * FILL_RB, 1024, 40960>>>(out);
}